// round 7
// baseline (speedup 1.0000x reference)
#include <cuda_runtime.h>

#define BHN   128
#define SEQ   4096
#define DIM   64
#define SPLIT 16
#define RPS   (SEQ / SPLIT)   // 256
#define CHUNK 32
#define NCH   (RPS / CHUNK)   // 8
#define EPSF  1e-6f

typedef unsigned long long u64;

// Scratch (device globals: allocation-free per harness rules)
__device__ float g_ctx_partial[BHN * SPLIT * DIM * DIM]; // 33.5 MB
__device__ float g_cs_partial [BHN * SPLIT * DIM];
__device__ float g_ctx        [BHN * DIM * DIM];         // 2 MB natural [d][e]

__device__ __forceinline__ void fma2(u64 &d, u64 a, u64 b) {
    asm("fma.rn.f32x2 %0, %1, %2, %0;" : "+l"(d) : "l"(a), "l"(b));
}
__device__ __forceinline__ float2 unpack2(u64 a) {
    float2 f; asm("mov.b64 {%0, %1}, %2;" : "=f"(f.x), "=f"(f.y) : "l"(a)); return f;
}
__device__ __forceinline__ u64 swap2(u64 a) {
    u64 r;
    asm("{\n\t.reg .b32 lo, hi;\n\tmov.b64 {lo,hi}, %1;\n\tmov.b64 %0, {hi,lo};\n\t}"
        : "=l"(r) : "l"(a));
    return r;
}
__device__ __forceinline__ void cp16(void* dst, const void* src) {
    unsigned s = (unsigned)__cvta_generic_to_shared(dst);
    asm volatile("cp.async.cg.shared.global [%0], [%1], 16;" :: "r"(s), "l"(src));
}

#define EK_STR 68
#define V_STR  68

// ============================================================================
// Kernel 1: partial ctx[d][e] = sum_n e^{K[n][d]} * V[n][e] over an n-split.
// Double-buffered: V via cp.async.cg (bypasses L1/regs), K software-pipelined
// (LDG for ch+1 issued before inner(ch); exp+STS into the idle buffer).
// Per-thread GEMM tile: 4 d x 8 e, diag/anti natural pairs (3 LDS + 16 FFMA2/n).
// ============================================================================
__global__ __launch_bounds__(128, 5)
void ctx_kernel(const float* __restrict__ kp, const float* __restrict__ vp)
{
    __shared__ __align__(16) float s_ek[2][CHUNK * EK_STR]; // 17 KB
    __shared__ __align__(16) float s_v [2][CHUNK * V_STR];  // 17 KB
    __shared__ __align__(16) float s_red[8 * DIM];          //  2 KB

    const int tid = threadIdx.x;
    const int w = tid >> 5, l = tid & 31;
    const int dbase = 16 * w + 4 * (l >> 3);
    const int eg = l & 7;
    const int hh = tid >> 4, dcol = tid & 15;
    const int split = blockIdx.x, bh = blockIdx.y;
    const size_t base = ((size_t)bh * SEQ + (size_t)split * RPS) * DIM;

    u64 accD[2][4], accA[2][4];
#pragma unroll
    for (int i = 0; i < 2; i++)
#pragma unroll
        for (int j = 0; j < 4; j++) { accD[i][j] = 0ull; accA[i][j] = 0ull; }
    float4 cs = make_float4(0.f, 0.f, 0.f, 0.f);

    // ---- prologue: stage chunk 0 ----
    {
#pragma unroll
        for (int r = 0; r < 4; r++) {
            const int nl = 8 * r + hh;
            cp16(&s_v[0][nl * V_STR + 4 * dcol],
                 vp + base + (size_t)nl * DIM + 4 * dcol);
        }
        asm volatile("cp.async.commit_group;");
        float4 kk[4];
#pragma unroll
        for (int r = 0; r < 4; r++) {
            const int nl = 8 * r + hh;
            kk[r] = *(const float4*)(kp + base + (size_t)nl * DIM + 4 * dcol);
        }
#pragma unroll
        for (int r = 0; r < 4; r++) {
            const int nl = 8 * r + hh;
            const float e0 = __expf(kk[r].x), e1 = __expf(kk[r].y),
                        e2 = __expf(kk[r].z), e3 = __expf(kk[r].w);
            cs.x += e0; cs.y += e1; cs.z += e2; cs.w += e3;
            *(float4*)&s_ek[0][nl * EK_STR + 4 * dcol] = make_float4(e0, e1, e2, e3);
        }
        asm volatile("cp.async.wait_group 0;");
        __syncthreads();
    }

    for (int ch = 0; ch < NCH; ch++) {
        const int p = ch & 1;
        float4 kk[4];
        if (ch + 1 < NCH) {
            const size_t nb = base + (size_t)(ch + 1) * CHUNK * DIM;
#pragma unroll
            for (int r = 0; r < 4; r++) {
                const int nl = 8 * r + hh;
                cp16(&s_v[1 - p][nl * V_STR + 4 * dcol],
                     vp + nb + (size_t)nl * DIM + 4 * dcol);
            }
            asm volatile("cp.async.commit_group;");
#pragma unroll
            for (int r = 0; r < 4; r++) {
                const int nl = 8 * r + hh;
                kk[r] = *(const float4*)(kp + nb + (size_t)nl * DIM + 4 * dcol);
            }
        }

        // ---- inner: rank-1 updates on buffer p ----
        const float* ekb = s_ek[p];
        const float* vb  = s_v[p];
#pragma unroll 8
        for (int n = 0; n < CHUNK; n++) {
            const ulonglong2 dd = *(const ulonglong2*)&ekb[n * EK_STR + dbase];
            const u64 s0 = swap2(dd.x), s1 = swap2(dd.y);
            const ulonglong2 v0 = *(const ulonglong2*)&vb[n * V_STR + 4 * eg];
            const ulonglong2 v1 = *(const ulonglong2*)&vb[n * V_STR + 32 + 4 * eg];
            fma2(accD[0][0], dd.x, v0.x); fma2(accA[0][0], s0, v0.x);
            fma2(accD[0][1], dd.x, v0.y); fma2(accA[0][1], s0, v0.y);
            fma2(accD[0][2], dd.x, v1.x); fma2(accA[0][2], s0, v1.x);
            fma2(accD[0][3], dd.x, v1.y); fma2(accA[0][3], s0, v1.y);
            fma2(accD[1][0], dd.y, v0.x); fma2(accA[1][0], s1, v0.x);
            fma2(accD[1][1], dd.y, v0.y); fma2(accA[1][1], s1, v0.y);
            fma2(accD[1][2], dd.y, v1.x); fma2(accA[1][2], s1, v1.x);
            fma2(accD[1][3], dd.y, v1.y); fma2(accA[1][3], s1, v1.y);
        }

        if (ch + 1 < NCH) {
#pragma unroll
            for (int r = 0; r < 4; r++) {
                const int nl = 8 * r + hh;
                const float e0 = __expf(kk[r].x), e1 = __expf(kk[r].y),
                            e2 = __expf(kk[r].z), e3 = __expf(kk[r].w);
                cs.x += e0; cs.y += e1; cs.z += e2; cs.w += e3;
                *(float4*)&s_ek[1 - p][nl * EK_STR + 4 * dcol] =
                    make_float4(e0, e1, e2, e3);
            }
            asm volatile("cp.async.wait_group 0;");
        }
        __syncthreads();
    }

    // ---- colsum partial ----
    *(float4*)&s_red[hh * DIM + 4 * dcol] = cs;
    __syncthreads();
    const int pbase = bh * SPLIT + split;
    if (tid < DIM) {
        float s = 0.f;
#pragma unroll
        for (int y = 0; y < 8; y++) s += s_red[y * DIM + tid];
        g_cs_partial[pbase * DIM + tid] = s;
    }

    // ---- context partial ----
    float* cp = g_ctx_partial + (size_t)pbase * DIM * DIM;
#pragma unroll
    for (int p2 = 0; p2 < 2; p2++) {
        const float2 D0 = unpack2(accD[p2][0]), A0 = unpack2(accA[p2][0]);
        const float2 D1 = unpack2(accD[p2][1]), A1 = unpack2(accA[p2][1]);
        const float2 D2 = unpack2(accD[p2][2]), A2 = unpack2(accA[p2][2]);
        const float2 D3 = unpack2(accD[p2][3]), A3 = unpack2(accA[p2][3]);
        float* r0 = cp + (size_t)(dbase + 2 * p2) * DIM;
        float* r1 = r0 + DIM;
        *(float4*)(r0 + 4 * eg)      = make_float4(D0.x, A0.y, D1.x, A1.y);
        *(float4*)(r0 + 32 + 4 * eg) = make_float4(D2.x, A2.y, D3.x, A3.y);
        *(float4*)(r1 + 4 * eg)      = make_float4(A0.x, D0.y, A1.x, D1.y);
        *(float4*)(r1 + 32 + 4 * eg) = make_float4(A2.x, D2.y, A3.x, D3.y);
    }
}

// ============================================================================
// Kernel 2: reduce split partials, normalize, emit NATURAL fp32 context.
// ============================================================================
__global__ __launch_bounds__(256)
void reduce_kernel()
{
    const int bh = blockIdx.x, tid = threadIdx.x;
    __shared__ float inv[DIM];
    if (tid < DIM) {
        float s = 0.f;
#pragma unroll
        for (int sp = 0; sp < SPLIT; sp++)
            s += g_cs_partial[(bh * SPLIT + sp) * DIM + tid];
        inv[tid] = 1.0f / (s * (1.0f + EPSF));
    }
    __syncthreads();
#pragma unroll
    for (int r = 0; r < 4; r++) {
        const int i4 = r * 256 + tid;
        float4 s = make_float4(0.f, 0.f, 0.f, 0.f);
#pragma unroll
        for (int sp = 0; sp < SPLIT; sp++) {
            const float4 p = *(const float4*)(g_ctx_partial +
                (size_t)(bh * SPLIT + sp) * DIM * DIM + 4 * i4);
            s.x += p.x; s.y += p.y; s.z += p.z; s.w += p.w;
        }
        const float iv = inv[i4 >> 4];
        s.x *= iv; s.y *= iv; s.z *= iv; s.w *= iv;
        *(float4*)(g_ctx + (size_t)bh * DIM * DIM + 4 * i4) = s;
    }
}

// ============================================================================
// Kernel 3: out = rowsoftmax(Q) @ ctx.  128 threads, 128 n-rows per block.
// p^T stored with part-XOR column swizzle: column = n ^ (16 * (d>>5)).
//  -> scalar transpose STS are CONFLICT-FREE (1 wavefront each).
// GEMM d-loop split into halves so the XOR is hoisted (nbase vs nbase^16).
// ============================================================================
#define ONB    128
#define PT_STR 128
#define C_STR  68

__global__ __launch_bounds__(128, 4)
void out_kernel(const float* __restrict__ qp, float* __restrict__ outp)
{
    __shared__ __align__(16) float s_pT[DIM * PT_STR]; // 32 KB
    __shared__ __align__(16) float s_c [DIM * C_STR];  // 17 KB

    const int tid = threadIdx.x;
    const int w = tid >> 5, l = tid & 31;
    const int nbase = 32 * w + 8 * (l >> 3);
    const int eg = l & 7;
    const int nb = blockIdx.x, bh = blockIdx.y;

    // stage natural ctx
    {
        const float4* src = (const float4*)(g_ctx + (size_t)bh * DIM * DIM);
#pragma unroll
        for (int r = 0; r < 8; r++) {
            const int i = r * 128 + tid;
            const int d = i >> 4, c = i & 15;
            *(float4*)&s_c[d * C_STR + 4 * c] = src[i];
        }
    }

    // row softmax of q: 2 threads per row; swizzled conflict-free transpose store
#pragma unroll
    for (int pass = 0; pass < 2; pass++) {
        const int row = 64 * pass + (tid >> 1), part = tid & 1;
        const float* qr = qp + ((size_t)bh * SEQ + (size_t)nb * ONB + row) * DIM + part * 32;
        float e[32];
#pragma unroll
        for (int i = 0; i < 8; i++) {
            const float4 a = *(const float4*)(qr + 4 * i);
            e[4*i] = a.x; e[4*i+1] = a.y; e[4*i+2] = a.z; e[4*i+3] = a.w;
        }
        float m = e[0];
#pragma unroll
        for (int i = 1; i < 32; i++) m = fmaxf(m, e[i]);
        m = fmaxf(m, __shfl_xor_sync(0xffffffffu, m, 1));
        float s = 0.f;
#pragma unroll
        for (int i = 0; i < 32; i++) { e[i] = __expf(e[i] - m); s += e[i]; }
        s += __shfl_xor_sync(0xffffffffu, s, 1);
        const float rinv = 1.0f / s;
        const int col = row ^ (16 * part);             // d>=32 rows get XOR'd column
#pragma unroll
        for (int i = 0; i < 32; i++)
            s_pT[(32 * part + i) * PT_STR + col] = e[i] * rinv;
    }
    __syncthreads();

    // GEMM: out[n][e] = sum_d p[n][d] * ctx[d][e]
    u64 accD[4][4], accA[4][4];
#pragma unroll
    for (int i = 0; i < 4; i++)
#pragma unroll
        for (int j = 0; j < 4; j++) { accD[i][j] = 0ull; accA[i][j] = 0ull; }

#pragma unroll
    for (int half = 0; half < 2; half++) {
        const int nbe = half ? (nbase ^ 16) : nbase;   // undo store swizzle
#pragma unroll 8
        for (int dl = 0; dl < 32; dl++) {
            const int d = 32 * half + dl;
            const float* pd = s_pT + d * PT_STR + nbe;
            const ulonglong2 pA = *(const ulonglong2*)(pd);
            const ulonglong2 pB = *(const ulonglong2*)(pd + 4);
            const u64 sA0 = swap2(pA.x), sA1 = swap2(pA.y);
            const u64 sB0 = swap2(pB.x), sB1 = swap2(pB.y);
            const float* cd = s_c + d * C_STR;
            const ulonglong2 c0 = *(const ulonglong2*)(cd + 4 * eg);
            const ulonglong2 c1 = *(const ulonglong2*)(cd + 32 + 4 * eg);
            fma2(accD[0][0], pA.x, c0.x); fma2(accA[0][0], sA0, c0.x);
            fma2(accD[0][1], pA.x, c0.y); fma2(accA[0][1], sA0, c0.y);
            fma2(accD[0][2], pA.x, c1.x); fma2(accA[0][2], sA0, c1.x);
            fma2(accD[0][3], pA.x, c1.y); fma2(accA[0][3], sA0, c1.y);
            fma2(accD[1][0], pA.y, c0.x); fma2(accA[1][0], sA1, c0.x);
            fma2(accD[1][1], pA.y, c0.y); fma2(accA[1][1], sA1, c0.y);
            fma2(accD[1][2], pA.y, c1.x); fma2(accA[1][2], sA1, c1.x);
            fma2(accD[1][3], pA.y, c1.y); fma2(accA[1][3], sA1, c1.y);
            fma2(accD[2][0], pB.x, c0.x); fma2(accA[2][0], sB0, c0.x);
            fma2(accD[2][1], pB.x, c0.y); fma2(accA[2][1], sB0, c0.y);
            fma2(accD[2][2], pB.x, c1.x); fma2(accA[2][2], sB0, c1.x);
            fma2(accD[2][3], pB.x, c1.y); fma2(accA[2][3], sB0, c1.y);
            fma2(accD[3][0], pB.y, c0.x); fma2(accA[3][0], sB1, c0.x);
            fma2(accD[3][1], pB.y, c0.y); fma2(accA[3][1], sB1, c0.y);
            fma2(accD[3][2], pB.y, c1.x); fma2(accA[3][2], sB1, c1.x);
            fma2(accD[3][3], pB.y, c1.y); fma2(accA[3][3], sB1, c1.y);
        }
    }

    // epilogue
    const size_t obase = ((size_t)bh * SEQ + (size_t)nb * ONB) * DIM;
#pragma unroll
    for (int p = 0; p < 4; p++) {
        const float2 D0 = unpack2(accD[p][0]), A0 = unpack2(accA[p][0]);
        const float2 D1 = unpack2(accD[p][1]), A1 = unpack2(accA[p][1]);
        const float2 D2 = unpack2(accD[p][2]), A2 = unpack2(accA[p][2]);
        const float2 D3 = unpack2(accD[p][3]), A3 = unpack2(accA[p][3]);
        float* r0 = outp + obase + (size_t)(nbase + 2 * p) * DIM;
        float* r1 = r0 + DIM;
        *(float4*)(r0 + 4 * eg)      = make_float4(D0.x, A0.y, D1.x, A1.y);
        *(float4*)(r0 + 32 + 4 * eg) = make_float4(D2.x, A2.y, D3.x, A3.y);
        *(float4*)(r1 + 4 * eg)      = make_float4(A0.x, D0.y, A1.x, D1.y);
        *(float4*)(r1 + 32 + 4 * eg) = make_float4(A2.x, D2.y, A3.x, D3.y);
    }
}

// ============================================================================
extern "C" void kernel_launch(void* const* d_in, const int* in_sizes, int n_in,
                              void* d_out, int out_size)
{
    const float* q = (const float*)d_in[0];
    const float* k = (const float*)d_in[1];
    const float* v = (const float*)d_in[2];
    float* out = (float*)d_out;

    ctx_kernel  <<<dim3(SPLIT, BHN), 128>>>(k, v);
    reduce_kernel<<<BHN, 256>>>();
    out_kernel  <<<dim3(SEQ / ONB, BHN), 128>>>(q, out);
}

// round 8
// speedup vs baseline: 1.0070x; 1.0070x over previous
#include <cuda_runtime.h>

#define BHN   128
#define SEQ   4096
#define DIM   64
#define SPLIT 16
#define RPS   (SEQ / SPLIT)   // 256
#define CHUNK 32
#define NCH   (RPS / CHUNK)   // 8
#define EPSF  1e-6f

typedef unsigned long long u64;

// Scratch (device globals: allocation-free per harness rules)
__device__ float g_ctx_partial[BHN * SPLIT * DIM * DIM]; // 33.5 MB
__device__ float g_cs_partial [BHN * SPLIT * DIM];
__device__ float g_ctx        [BHN * DIM * DIM];         // 2 MB natural [d][e]

__device__ __forceinline__ void fma2(u64 &d, u64 a, u64 b) {
    asm("fma.rn.f32x2 %0, %1, %2, %0;" : "+l"(d) : "l"(a), "l"(b));
}
__device__ __forceinline__ float2 unpack2(u64 a) {
    float2 f; asm("mov.b64 {%0, %1}, %2;" : "=f"(f.x), "=f"(f.y) : "l"(a)); return f;
}
__device__ __forceinline__ u64 swap2(u64 a) {
    u64 r;
    asm("{\n\t.reg .b32 lo, hi;\n\tmov.b64 {lo,hi}, %1;\n\tmov.b64 %0, {hi,lo};\n\t}"
        : "=l"(r) : "l"(a));
    return r;
}

#define EK_STR 68
#define V_STR  68

// ============================================================================
// Kernel 1: partial ctx[d][e] = sum_n e^{K[n][d]} * V[n][e] over an n-split.
// 64 threads (2 warps). Per-thread tile: 8 d x 8 e, diag/anti natural pairs.
//  warp w, lane l:  dbase = 32w + 8*(l>>3)  (d rows dbase..dbase+7)
//                   eg = l&7 -> e cols {4eg..4eg+3} u {32+4eg..+3}
// Inner per n: 4 LDS.128 + 4 swap + 32 FFMA2  (64 MACs -> 0.0625 LSU-inst/MAC).
// ============================================================================
__global__ __launch_bounds__(64, 8)
void ctx_kernel(const float* __restrict__ kp, const float* __restrict__ vp)
{
    __shared__ __align__(16) float s_ek[CHUNK * EK_STR]; // 8.5 KB natural [n][d]
    __shared__ __align__(16) float s_v [CHUNK * V_STR];  // 8.5 KB natural [n][e]
    __shared__ __align__(16) float s_red[4 * DIM];       // 1 KB

    const int tid = threadIdx.x;
    const int w = tid >> 5, l = tid & 31;
    const int dbase = 32 * w + 8 * (l >> 3);
    const int eg = l & 7;
    const int hh = tid >> 4, dcol = tid & 15;        // staging coords (hh 0..3)
    const int split = blockIdx.x, bh = blockIdx.y;
    const size_t base = ((size_t)bh * SEQ + (size_t)split * RPS) * DIM;

    u64 accD[4][4], accA[4][4];                      // [d-pair][e-pair]
#pragma unroll
    for (int i = 0; i < 4; i++)
#pragma unroll
        for (int j = 0; j < 4; j++) { accD[i][j] = 0ull; accA[i][j] = 0ull; }
    float4 cs = make_float4(0.f, 0.f, 0.f, 0.f);     // colsum for d=4dcol..+3

    for (int ch = 0; ch < NCH; ch++) {
        // ---- stage chunk (natural layouts, padded stride) ----
#pragma unroll
        for (int r = 0; r < 8; r++) {
            const int nl = 4 * r + hh;               // 0..31
            const size_t goff = base + (size_t)(ch * CHUNK + nl) * DIM + 4 * dcol;
            const float4 kk = *(const float4*)(kp + goff);
            const float e0 = __expf(kk.x), e1 = __expf(kk.y),
                        e2 = __expf(kk.z), e3 = __expf(kk.w);
            cs.x += e0; cs.y += e1; cs.z += e2; cs.w += e3;
            *(float4*)&s_ek[nl * EK_STR + 4 * dcol] = make_float4(e0, e1, e2, e3);
            *(float4*)&s_v [nl * V_STR  + 4 * dcol] = *(const float4*)(vp + goff);
        }
        __syncthreads();

        // ---- rank-1 updates ----
#pragma unroll 8
        for (int n = 0; n < CHUNK; n++) {
            const float* ekn = s_ek + n * EK_STR + dbase;
            const ulonglong2 dA = *(const ulonglong2*)(ekn);     // (d0,d1),(d2,d3)
            const ulonglong2 dB = *(const ulonglong2*)(ekn + 4); // (d4,d5),(d6,d7)
            const u64 s0 = swap2(dA.x), s1 = swap2(dA.y);
            const u64 s2 = swap2(dB.x), s3 = swap2(dB.y);
            const float* vn = s_v + n * V_STR;
            const ulonglong2 v0 = *(const ulonglong2*)(vn + 4 * eg);      // (e0,e1),(e2,e3)
            const ulonglong2 v1 = *(const ulonglong2*)(vn + 32 + 4 * eg); // (E0,E1),(E2,E3)

            fma2(accD[0][0], dA.x, v0.x); fma2(accA[0][0], s0, v0.x);
            fma2(accD[0][1], dA.x, v0.y); fma2(accA[0][1], s0, v0.y);
            fma2(accD[0][2], dA.x, v1.x); fma2(accA[0][2], s0, v1.x);
            fma2(accD[0][3], dA.x, v1.y); fma2(accA[0][3], s0, v1.y);
            fma2(accD[1][0], dA.y, v0.x); fma2(accA[1][0], s1, v0.x);
            fma2(accD[1][1], dA.y, v0.y); fma2(accA[1][1], s1, v0.y);
            fma2(accD[1][2], dA.y, v1.x); fma2(accA[1][2], s1, v1.x);
            fma2(accD[1][3], dA.y, v1.y); fma2(accA[1][3], s1, v1.y);
            fma2(accD[2][0], dB.x, v0.x); fma2(accA[2][0], s2, v0.x);
            fma2(accD[2][1], dB.x, v0.y); fma2(accA[2][1], s2, v0.y);
            fma2(accD[2][2], dB.x, v1.x); fma2(accA[2][2], s2, v1.x);
            fma2(accD[2][3], dB.x, v1.y); fma2(accA[2][3], s2, v1.y);
            fma2(accD[3][0], dB.y, v0.x); fma2(accA[3][0], s3, v0.x);
            fma2(accD[3][1], dB.y, v0.y); fma2(accA[3][1], s3, v0.y);
            fma2(accD[3][2], dB.y, v1.x); fma2(accA[3][2], s3, v1.x);
            fma2(accD[3][3], dB.y, v1.y); fma2(accA[3][3], s3, v1.y);
        }
        __syncthreads();
    }

    // ---- colsum partial ----
    *(float4*)&s_red[hh * DIM + 4 * dcol] = cs;
    __syncthreads();
    const int pbase = bh * SPLIT + split;
    {
        float s = 0.f;
#pragma unroll
        for (int y = 0; y < 4; y++) s += s_red[y * DIM + tid];
        g_cs_partial[pbase * DIM + tid] = s;
    }

    // ---- context partial (plain [d][e]) ----
    // block (d0,d1)x(e0,e1): row d0 = (D.x, A.y); row d1 = (A.x, D.y)
    float* cp = g_ctx_partial + (size_t)pbase * DIM * DIM;
#pragma unroll
    for (int dp = 0; dp < 4; dp++) {
        const float2 D0 = unpack2(accD[dp][0]), A0 = unpack2(accA[dp][0]);
        const float2 D1 = unpack2(accD[dp][1]), A1 = unpack2(accA[dp][1]);
        const float2 D2 = unpack2(accD[dp][2]), A2 = unpack2(accA[dp][2]);
        const float2 D3 = unpack2(accD[dp][3]), A3 = unpack2(accA[dp][3]);
        float* r0 = cp + (size_t)(dbase + 2 * dp) * DIM;
        float* r1 = r0 + DIM;
        *(float4*)(r0 + 4 * eg)      = make_float4(D0.x, A0.y, D1.x, A1.y);
        *(float4*)(r0 + 32 + 4 * eg) = make_float4(D2.x, A2.y, D3.x, A3.y);
        *(float4*)(r1 + 4 * eg)      = make_float4(A0.x, D0.y, A1.x, D1.y);
        *(float4*)(r1 + 32 + 4 * eg) = make_float4(A2.x, D2.y, A3.x, D3.y);
    }
}

// ============================================================================
// Kernel 2: reduce split partials, normalize, emit NATURAL fp32 context.
// ============================================================================
__global__ __launch_bounds__(256)
void reduce_kernel()
{
    const int bh = blockIdx.x, tid = threadIdx.x;
    __shared__ float inv[DIM];
    if (tid < DIM) {
        float s = 0.f;
#pragma unroll
        for (int sp = 0; sp < SPLIT; sp++)
            s += g_cs_partial[(bh * SPLIT + sp) * DIM + tid];
        inv[tid] = 1.0f / (s * (1.0f + EPSF));
    }
    __syncthreads();
#pragma unroll
    for (int r = 0; r < 4; r++) {
        const int i4 = r * 256 + tid;
        float4 s = make_float4(0.f, 0.f, 0.f, 0.f);
#pragma unroll
        for (int sp = 0; sp < SPLIT; sp++) {
            const float4 p = *(const float4*)(g_ctx_partial +
                (size_t)(bh * SPLIT + sp) * DIM * DIM + 4 * i4);
            s.x += p.x; s.y += p.y; s.z += p.z; s.w += p.w;
        }
        const float iv = inv[i4 >> 4];
        s.x *= iv; s.y *= iv; s.z *= iv; s.w *= iv;
        *(float4*)(g_ctx + (size_t)bh * DIM * DIM + 4 * i4) = s;
    }
}

// ============================================================================
// Kernel 3: out = rowsoftmax(Q) @ ctx.  128 threads, 128 n-rows per block.
// (exact R6 version — measured best)
// ============================================================================
#define ONB    128
#define PT_STR 128
#define C_STR  68

__global__ __launch_bounds__(128, 4)
void out_kernel(const float* __restrict__ qp, float* __restrict__ outp)
{
    __shared__ __align__(16) float s_pT[DIM * PT_STR]; // 32 KB  p^T [d][n]
    __shared__ __align__(16) float s_c [DIM * C_STR];  // 17 KB  natural ctx [d][e]

    const int tid = threadIdx.x;
    const int w = tid >> 5, l = tid & 31;
    const int nbase = 32 * w + 8 * (l >> 3);
    const int eg = l & 7;
    const int nb = blockIdx.x, bh = blockIdx.y;

    // stage natural ctx (padded stride)
    {
        const float4* src = (const float4*)(g_ctx + (size_t)bh * DIM * DIM);
#pragma unroll
        for (int r = 0; r < 8; r++) {
            const int i = r * 128 + tid;             // i = d*16 + c
            const int d = i >> 4, c = i & 15;
            *(float4*)&s_c[d * C_STR + 4 * c] = src[i];
        }
    }

    // row softmax of q: 2 threads per row, 2 passes of 64 rows
#pragma unroll
    for (int pass = 0; pass < 2; pass++) {
        const int row = 64 * pass + (tid >> 1), part = tid & 1;
        const float* qr = qp + ((size_t)bh * SEQ + (size_t)nb * ONB + row) * DIM + part * 32;
        float e[32];
#pragma unroll
        for (int i = 0; i < 8; i++) {
            const float4 a = *(const float4*)(qr + 4 * i);
            e[4*i] = a.x; e[4*i+1] = a.y; e[4*i+2] = a.z; e[4*i+3] = a.w;
        }
        float m = e[0];
#pragma unroll
        for (int i = 1; i < 32; i++) m = fmaxf(m, e[i]);
        m = fmaxf(m, __shfl_xor_sync(0xffffffffu, m, 1));
        float s = 0.f;
#pragma unroll
        for (int i = 0; i < 32; i++) { e[i] = __expf(e[i] - m); s += e[i]; }
        s += __shfl_xor_sync(0xffffffffu, s, 1);
        const float rinv = 1.0f / s;
#pragma unroll
        for (int i = 0; i < 32; i++)
            s_pT[(32 * part + i) * PT_STR + row] = e[i] * rinv;
    }
    __syncthreads();

    // GEMM: out[n][e] = sum_d p[n][d] * ctx[d][e]
    u64 accD[4][4], accA[4][4];                      // [n-pair][e-pair]
#pragma unroll
    for (int i = 0; i < 4; i++)
#pragma unroll
        for (int j = 0; j < 4; j++) { accD[i][j] = 0ull; accA[i][j] = 0ull; }

#pragma unroll 8
    for (int d = 0; d < DIM; d++) {
        const float* pd = s_pT + d * PT_STR + nbase;
        const ulonglong2 pA = *(const ulonglong2*)(pd);       // (n0,n1),(n2,n3)
        const ulonglong2 pB = *(const ulonglong2*)(pd + 4);   // (n4,n5),(n6,n7)
        const u64 sA0 = swap2(pA.x), sA1 = swap2(pA.y);
        const u64 sB0 = swap2(pB.x), sB1 = swap2(pB.y);
        const float* cd = s_c + d * C_STR;
        const ulonglong2 c0 = *(const ulonglong2*)(cd + 4 * eg);      // (e0,e1),(e2,e3)
        const ulonglong2 c1 = *(const ulonglong2*)(cd + 32 + 4 * eg); // (E0,E1),(E2,E3)
        fma2(accD[0][0], pA.x, c0.x); fma2(accA[0][0], sA0, c0.x);
        fma2(accD[0][1], pA.x, c0.y); fma2(accA[0][1], sA0, c0.y);
        fma2(accD[0][2], pA.x, c1.x); fma2(accA[0][2], sA0, c1.x);
        fma2(accD[0][3], pA.x, c1.y); fma2(accA[0][3], sA0, c1.y);
        fma2(accD[1][0], pA.y, c0.x); fma2(accA[1][0], sA1, c0.x);
        fma2(accD[1][1], pA.y, c0.y); fma2(accA[1][1], sA1, c0.y);
        fma2(accD[1][2], pA.y, c1.x); fma2(accA[1][2], sA1, c1.x);
        fma2(accD[1][3], pA.y, c1.y); fma2(accA[1][3], sA1, c1.y);
        fma2(accD[2][0], pB.x, c0.x); fma2(accA[2][0], sB0, c0.x);
        fma2(accD[2][1], pB.x, c0.y); fma2(accA[2][1], sB0, c0.y);
        fma2(accD[2][2], pB.x, c1.x); fma2(accA[2][2], sB0, c1.x);
        fma2(accD[2][3], pB.x, c1.y); fma2(accA[2][3], sB0, c1.y);
        fma2(accD[3][0], pB.y, c0.x); fma2(accA[3][0], sB1, c0.x);
        fma2(accD[3][1], pB.y, c0.y); fma2(accA[3][1], sB1, c0.y);
        fma2(accD[3][2], pB.y, c1.x); fma2(accA[3][2], sB1, c1.x);
        fma2(accD[3][3], pB.y, c1.y); fma2(accA[3][3], sB1, c1.y);
    }

    // epilogue: block (n0,n1)x(e0,e1): row n0 = (D.x, A.y); row n1 = (A.x, D.y)
    const size_t obase = ((size_t)bh * SEQ + (size_t)nb * ONB) * DIM;
#pragma unroll
    for (int p = 0; p < 4; p++) {
        const float2 D0 = unpack2(accD[p][0]), A0 = unpack2(accA[p][0]);
        const float2 D1 = unpack2(accD[p][1]), A1 = unpack2(accA[p][1]);
        const float2 D2 = unpack2(accD[p][2]), A2 = unpack2(accA[p][2]);
        const float2 D3 = unpack2(accD[p][3]), A3 = unpack2(accA[p][3]);
        float* r0 = outp + obase + (size_t)(nbase + 2 * p) * DIM;
        float* r1 = r0 + DIM;
        *(float4*)(r0 + 4 * eg)      = make_float4(D0.x, A0.y, D1.x, A1.y);
        *(float4*)(r0 + 32 + 4 * eg) = make_float4(D2.x, A2.y, D3.x, A3.y);
        *(float4*)(r1 + 4 * eg)      = make_float4(A0.x, D0.y, A1.x, D1.y);
        *(float4*)(r1 + 32 + 4 * eg) = make_float4(A2.x, D2.y, A3.x, D3.y);
    }
}

// ============================================================================
extern "C" void kernel_launch(void* const* d_in, const int* in_sizes, int n_in,
                              void* d_out, int out_size)
{
    const float* q = (const float*)d_in[0];
    const float* k = (const float*)d_in[1];
    const float* v = (const float*)d_in[2];
    float* out = (float*)d_out;

    ctx_kernel  <<<dim3(SPLIT, BHN), 64>>>(k, v);
    reduce_kernel<<<BHN, 256>>>();
    out_kernel  <<<dim3(SEQ / ONB, BHN), 128>>>(q, out);
}

// round 9
// speedup vs baseline: 1.4792x; 1.4690x over previous
#include <cuda_runtime.h>

#define BHN   128
#define SEQ   4096
#define DIM   64
#define SPLIT 8
#define RPS   (SEQ / SPLIT)   // 512
#define CHUNK 32
#define NCH   (RPS / CHUNK)   // 16
#define EPSF  1e-6f

typedef unsigned long long u64;

// Scratch (device globals: allocation-free per harness rules)
__device__ float g_ctx_partial[BHN * SPLIT * DIM * DIM]; // 16.8 MB
__device__ float g_cs_partial [BHN * SPLIT * DIM];
__device__ float g_ctx        [BHN * DIM * DIM];         // 2 MB natural [d][e]

__device__ __forceinline__ void fma2(u64 &d, u64 a, u64 b) {
    asm("fma.rn.f32x2 %0, %1, %2, %0;" : "+l"(d) : "l"(a), "l"(b));
}
__device__ __forceinline__ float2 unpack2(u64 a) {
    float2 f; asm("mov.b64 {%0, %1}, %2;" : "=f"(f.x), "=f"(f.y) : "l"(a)); return f;
}
__device__ __forceinline__ u64 swap2(u64 a) {
    u64 r;
    asm("{\n\t.reg .b32 lo, hi;\n\tmov.b64 {lo,hi}, %1;\n\tmov.b64 %0, {hi,lo};\n\t}"
        : "=l"(r) : "l"(a));
    return r;
}

#define EK_STR 68
#define V_STR  68

// ============================================================================
// Kernel 1: partial ctx[d][e] = sum_n e^{K[n][d]} * V[n][e] over an n-split.
// 64 threads (2 warps). Per-thread tile: 8 d x 8 e, diag/anti natural pairs.
// SPLIT=8 -> grid 1024 = ONE full wave at 8 blocks/SM (no ragged second wave).
// Inner per n: 4 LDS.128 + 4 swap + 32 FFMA2  (64 MACs).
// ============================================================================
__global__ __launch_bounds__(64, 8)
void ctx_kernel(const float* __restrict__ kp, const float* __restrict__ vp)
{
    __shared__ __align__(16) float s_ek[CHUNK * EK_STR]; // 8.5 KB natural [n][d]
    __shared__ __align__(16) float s_v [CHUNK * V_STR];  // 8.5 KB natural [n][e]
    __shared__ __align__(16) float s_red[4 * DIM];       // 1 KB

    const int tid = threadIdx.x;
    const int w = tid >> 5, l = tid & 31;
    const int dbase = 32 * w + 8 * (l >> 3);
    const int eg = l & 7;
    const int hh = tid >> 4, dcol = tid & 15;        // staging coords (hh 0..3)
    const int split = blockIdx.x, bh = blockIdx.y;
    const size_t base = ((size_t)bh * SEQ + (size_t)split * RPS) * DIM;

    u64 accD[4][4], accA[4][4];                      // [d-pair][e-pair]
#pragma unroll
    for (int i = 0; i < 4; i++)
#pragma unroll
        for (int j = 0; j < 4; j++) { accD[i][j] = 0ull; accA[i][j] = 0ull; }
    float4 cs = make_float4(0.f, 0.f, 0.f, 0.f);     // colsum for d=4dcol..+3

    for (int ch = 0; ch < NCH; ch++) {
        // ---- stage chunk (natural layouts, padded stride) ----
#pragma unroll
        for (int r = 0; r < 8; r++) {
            const int nl = 4 * r + hh;               // 0..31
            const size_t goff = base + (size_t)(ch * CHUNK + nl) * DIM + 4 * dcol;
            const float4 kk = *(const float4*)(kp + goff);
            const float e0 = __expf(kk.x), e1 = __expf(kk.y),
                        e2 = __expf(kk.z), e3 = __expf(kk.w);
            cs.x += e0; cs.y += e1; cs.z += e2; cs.w += e3;
            *(float4*)&s_ek[nl * EK_STR + 4 * dcol] = make_float4(e0, e1, e2, e3);
            *(float4*)&s_v [nl * V_STR  + 4 * dcol] = *(const float4*)(vp + goff);
        }
        __syncthreads();

        // ---- rank-1 updates ----
#pragma unroll 8
        for (int n = 0; n < CHUNK; n++) {
            const float* ekn = s_ek + n * EK_STR + dbase;
            const ulonglong2 dA = *(const ulonglong2*)(ekn);     // (d0,d1),(d2,d3)
            const ulonglong2 dB = *(const ulonglong2*)(ekn + 4); // (d4,d5),(d6,d7)
            const u64 s0 = swap2(dA.x), s1 = swap2(dA.y);
            const u64 s2 = swap2(dB.x), s3 = swap2(dB.y);
            const float* vn = s_v + n * V_STR;
            const ulonglong2 v0 = *(const ulonglong2*)(vn + 4 * eg);      // (e0,e1),(e2,e3)
            const ulonglong2 v1 = *(const ulonglong2*)(vn + 32 + 4 * eg); // (E0,E1),(E2,E3)

            fma2(accD[0][0], dA.x, v0.x); fma2(accA[0][0], s0, v0.x);
            fma2(accD[0][1], dA.x, v0.y); fma2(accA[0][1], s0, v0.y);
            fma2(accD[0][2], dA.x, v1.x); fma2(accA[0][2], s0, v1.x);
            fma2(accD[0][3], dA.x, v1.y); fma2(accA[0][3], s0, v1.y);
            fma2(accD[1][0], dA.y, v0.x); fma2(accA[1][0], s1, v0.x);
            fma2(accD[1][1], dA.y, v0.y); fma2(accA[1][1], s1, v0.y);
            fma2(accD[1][2], dA.y, v1.x); fma2(accA[1][2], s1, v1.x);
            fma2(accD[1][3], dA.y, v1.y); fma2(accA[1][3], s1, v1.y);
            fma2(accD[2][0], dB.x, v0.x); fma2(accA[2][0], s2, v0.x);
            fma2(accD[2][1], dB.x, v0.y); fma2(accA[2][1], s2, v0.y);
            fma2(accD[2][2], dB.x, v1.x); fma2(accA[2][2], s2, v1.x);
            fma2(accD[2][3], dB.x, v1.y); fma2(accA[2][3], s2, v1.y);
            fma2(accD[3][0], dB.y, v0.x); fma2(accA[3][0], s3, v0.x);
            fma2(accD[3][1], dB.y, v0.y); fma2(accA[3][1], s3, v0.y);
            fma2(accD[3][2], dB.y, v1.x); fma2(accA[3][2], s3, v1.x);
            fma2(accD[3][3], dB.y, v1.y); fma2(accA[3][3], s3, v1.y);
        }
        __syncthreads();
    }

    // ---- colsum partial ----
    *(float4*)&s_red[hh * DIM + 4 * dcol] = cs;
    __syncthreads();
    const int pbase = bh * SPLIT + split;
    {
        float s = 0.f;
#pragma unroll
        for (int y = 0; y < 4; y++) s += s_red[y * DIM + tid];
        g_cs_partial[pbase * DIM + tid] = s;
    }

    // ---- context partial (plain [d][e]) ----
    float* cp = g_ctx_partial + (size_t)pbase * DIM * DIM;
#pragma unroll
    for (int dp = 0; dp < 4; dp++) {
        const float2 D0 = unpack2(accD[dp][0]), A0 = unpack2(accA[dp][0]);
        const float2 D1 = unpack2(accD[dp][1]), A1 = unpack2(accA[dp][1]);
        const float2 D2 = unpack2(accD[dp][2]), A2 = unpack2(accA[dp][2]);
        const float2 D3 = unpack2(accD[dp][3]), A3 = unpack2(accA[dp][3]);
        float* r0 = cp + (size_t)(dbase + 2 * dp) * DIM;
        float* r1 = r0 + DIM;
        *(float4*)(r0 + 4 * eg)      = make_float4(D0.x, A0.y, D1.x, A1.y);
        *(float4*)(r0 + 32 + 4 * eg) = make_float4(D2.x, A2.y, D3.x, A3.y);
        *(float4*)(r1 + 4 * eg)      = make_float4(A0.x, D0.y, A1.x, D1.y);
        *(float4*)(r1 + 32 + 4 * eg) = make_float4(A2.x, D2.y, A3.x, D3.y);
    }
}

// ============================================================================
// Kernel 2: reduce split partials, normalize, emit NATURAL fp32 context.
// ============================================================================
__global__ __launch_bounds__(256)
void reduce_kernel()
{
    const int bh = blockIdx.x, tid = threadIdx.x;
    __shared__ float inv[DIM];
    if (tid < DIM) {
        float s = 0.f;
#pragma unroll
        for (int sp = 0; sp < SPLIT; sp++)
            s += g_cs_partial[(bh * SPLIT + sp) * DIM + tid];
        inv[tid] = 1.0f / (s * (1.0f + EPSF));
    }
    __syncthreads();
#pragma unroll
    for (int r = 0; r < 4; r++) {
        const int i4 = r * 256 + tid;
        float4 s = make_float4(0.f, 0.f, 0.f, 0.f);
#pragma unroll
        for (int sp = 0; sp < SPLIT; sp++) {
            const float4 p = *(const float4*)(g_ctx_partial +
                (size_t)(bh * SPLIT + sp) * DIM * DIM + 4 * i4);
            s.x += p.x; s.y += p.y; s.z += p.z; s.w += p.w;
        }
        const float iv = inv[i4 >> 4];
        s.x *= iv; s.y *= iv; s.z *= iv; s.w *= iv;
        *(float4*)(g_ctx + (size_t)bh * DIM * DIM + 4 * i4) = s;
    }
}

// ============================================================================
// Kernel 3: out = rowsoftmax(Q) @ ctx.  128 threads, 128 n-rows per block.
// (exact R6 version — measured best at high clock)
// ============================================================================
#define ONB    128
#define PT_STR 128
#define C_STR  68

__global__ __launch_bounds__(128, 4)
void out_kernel(const float* __restrict__ qp, float* __restrict__ outp)
{
    __shared__ __align__(16) float s_pT[DIM * PT_STR]; // 32 KB  p^T [d][n]
    __shared__ __align__(16) float s_c [DIM * C_STR];  // 17 KB  natural ctx [d][e]

    const int tid = threadIdx.x;
    const int w = tid >> 5, l = tid & 31;
    const int nbase = 32 * w + 8 * (l >> 3);
    const int eg = l & 7;
    const int nb = blockIdx.x, bh = blockIdx.y;

    // stage natural ctx (padded stride)
    {
        const float4* src = (const float4*)(g_ctx + (size_t)bh * DIM * DIM);
#pragma unroll
        for (int r = 0; r < 8; r++) {
            const int i = r * 128 + tid;             // i = d*16 + c
            const int d = i >> 4, c = i & 15;
            *(float4*)&s_c[d * C_STR + 4 * c] = src[i];
        }
    }

    // row softmax of q: 2 threads per row, 2 passes of 64 rows
#pragma unroll
    for (int pass = 0; pass < 2; pass++) {
        const int row = 64 * pass + (tid >> 1), part = tid & 1;
        const float* qr = qp + ((size_t)bh * SEQ + (size_t)nb * ONB + row) * DIM + part * 32;
        float e[32];
#pragma unroll
        for (int i = 0; i < 8; i++) {
            const float4 a = *(const float4*)(qr + 4 * i);
            e[4*i] = a.x; e[4*i+1] = a.y; e[4*i+2] = a.z; e[4*i+3] = a.w;
        }
        float m = e[0];
#pragma unroll
        for (int i = 1; i < 32; i++) m = fmaxf(m, e[i]);
        m = fmaxf(m, __shfl_xor_sync(0xffffffffu, m, 1));
        float s = 0.f;
#pragma unroll
        for (int i = 0; i < 32; i++) { e[i] = __expf(e[i] - m); s += e[i]; }
        s += __shfl_xor_sync(0xffffffffu, s, 1);
        const float rinv = 1.0f / s;
#pragma unroll
        for (int i = 0; i < 32; i++)
            s_pT[(32 * part + i) * PT_STR + row] = e[i] * rinv;
    }
    __syncthreads();

    // GEMM: out[n][e] = sum_d p[n][d] * ctx[d][e]
    u64 accD[4][4], accA[4][4];                      // [n-pair][e-pair]
#pragma unroll
    for (int i = 0; i < 4; i++)
#pragma unroll
        for (int j = 0; j < 4; j++) { accD[i][j] = 0ull; accA[i][j] = 0ull; }

#pragma unroll 8
    for (int d = 0; d < DIM; d++) {
        const float* pd = s_pT + d * PT_STR + nbase;
        const ulonglong2 pA = *(const ulonglong2*)(pd);       // (n0,n1),(n2,n3)
        const ulonglong2 pB = *(const ulonglong2*)(pd + 4);   // (n4,n5),(n6,n7)
        const u64 sA0 = swap2(pA.x), sA1 = swap2(pA.y);
        const u64 sB0 = swap2(pB.x), sB1 = swap2(pB.y);
        const float* cd = s_c + d * C_STR;
        const ulonglong2 c0 = *(const ulonglong2*)(cd + 4 * eg);      // (e0,e1),(e2,e3)
        const ulonglong2 c1 = *(const ulonglong2*)(cd + 32 + 4 * eg); // (E0,E1),(E2,E3)
        fma2(accD[0][0], pA.x, c0.x); fma2(accA[0][0], sA0, c0.x);
        fma2(accD[0][1], pA.x, c0.y); fma2(accA[0][1], sA0, c0.y);
        fma2(accD[0][2], pA.x, c1.x); fma2(accA[0][2], sA0, c1.x);
        fma2(accD[0][3], pA.x, c1.y); fma2(accA[0][3], sA0, c1.y);
        fma2(accD[1][0], pA.y, c0.x); fma2(accA[1][0], sA1, c0.x);
        fma2(accD[1][1], pA.y, c0.y); fma2(accA[1][1], sA1, c0.y);
        fma2(accD[1][2], pA.y, c1.x); fma2(accA[1][2], sA1, c1.x);
        fma2(accD[1][3], pA.y, c1.y); fma2(accA[1][3], sA1, c1.y);
        fma2(accD[2][0], pB.x, c0.x); fma2(accA[2][0], sB0, c0.x);
        fma2(accD[2][1], pB.x, c0.y); fma2(accA[2][1], sB0, c0.y);
        fma2(accD[2][2], pB.x, c1.x); fma2(accA[2][2], sB0, c1.x);
        fma2(accD[2][3], pB.x, c1.y); fma2(accA[2][3], sB0, c1.y);
        fma2(accD[3][0], pB.y, c0.x); fma2(accA[3][0], sB1, c0.x);
        fma2(accD[3][1], pB.y, c0.y); fma2(accA[3][1], sB1, c0.y);
        fma2(accD[3][2], pB.y, c1.x); fma2(accA[3][2], sB1, c1.x);
        fma2(accD[3][3], pB.y, c1.y); fma2(accA[3][3], sB1, c1.y);
    }

    // epilogue: block (n0,n1)x(e0,e1): row n0 = (D.x, A.y); row n1 = (A.x, D.y)
    const size_t obase = ((size_t)bh * SEQ + (size_t)nb * ONB) * DIM;
#pragma unroll
    for (int p = 0; p < 4; p++) {
        const float2 D0 = unpack2(accD[p][0]), A0 = unpack2(accA[p][0]);
        const float2 D1 = unpack2(accD[p][1]), A1 = unpack2(accA[p][1]);
        const float2 D2 = unpack2(accD[p][2]), A2 = unpack2(accA[p][2]);
        const float2 D3 = unpack2(accD[p][3]), A3 = unpack2(accA[p][3]);
        float* r0 = outp + obase + (size_t)(nbase + 2 * p) * DIM;
        float* r1 = r0 + DIM;
        *(float4*)(r0 + 4 * eg)      = make_float4(D0.x, A0.y, D1.x, A1.y);
        *(float4*)(r0 + 32 + 4 * eg) = make_float4(D2.x, A2.y, D3.x, A3.y);
        *(float4*)(r1 + 4 * eg)      = make_float4(A0.x, D0.y, A1.x, D1.y);
        *(float4*)(r1 + 32 + 4 * eg) = make_float4(A2.x, D2.y, A3.x, D3.y);
    }
}

// ============================================================================
extern "C" void kernel_launch(void* const* d_in, const int* in_sizes, int n_in,
                              void* d_out, int out_size)
{
    const float* q = (const float*)d_in[0];
    const float* k = (const float*)d_in[1];
    const float* v = (const float*)d_in[2];
    float* out = (float*)d_out;

    ctx_kernel  <<<dim3(SPLIT, BHN), 64>>>(k, v);
    reduce_kernel<<<BHN, 256>>>();
    out_kernel  <<<dim3(SEQ / ONB, BHN), 128>>>(q, out);
}

// round 10
// speedup vs baseline: 1.5389x; 1.0404x over previous
#include <cuda_runtime.h>

#define BHN   128
#define SEQ   4096
#define DIM   64
#define SPLIT 16
#define RPS   (SEQ / SPLIT)   // 256
#define CHUNK 16
#define NCH   (RPS / CHUNK)   // 16
#define EPSF  1e-6f

typedef unsigned long long u64;

// Scratch (device globals: allocation-free per harness rules)
__device__ float g_ctx_partial[BHN * SPLIT * DIM * DIM]; // 33.5 MB
__device__ float g_cs_partial [BHN * SPLIT * DIM];
__device__ float g_ctx        [BHN * DIM * DIM];         // 2 MB natural [d][e]

__device__ __forceinline__ void fma2(u64 &d, u64 a, u64 b) {
    asm("fma.rn.f32x2 %0, %1, %2, %0;" : "+l"(d) : "l"(a), "l"(b));
}
__device__ __forceinline__ float2 unpack2(u64 a) {
    float2 f; asm("mov.b64 {%0, %1}, %2;" : "=f"(f.x), "=f"(f.y) : "l"(a)); return f;
}
__device__ __forceinline__ u64 swap2(u64 a) {
    u64 r;
    asm("{\n\t.reg .b32 lo, hi;\n\tmov.b64 {lo,hi}, %1;\n\tmov.b64 %0, {hi,lo};\n\t}"
        : "=l"(r) : "l"(a));
    return r;
}
__device__ __forceinline__ void cp16(void* dst, const void* src) {
    unsigned s = (unsigned)__cvta_generic_to_shared(dst);
    asm volatile("cp.async.cg.shared.global [%0], [%1], 16;" :: "r"(s), "l"(src));
}

#define EK_STR 68
#define V_STR  68

// ============================================================================
// Kernel 1: partial ctx[d][e] = sum_n e^{K[n][d]} * V[n][e] over an n-split.
// 64 threads (2 warps), per-thread tile 8d x 8e (diag/anti natural pairs).
// CHUNK=16 double-buffered: V via cp.async.cg (no RF cost), K prefetched to
// regs before inner, exp+STS into idle buffer after inner. SPLIT=16 -> 2048
// blocks keeps every SM stocked.
// ============================================================================
__global__ __launch_bounds__(64, 7)
void ctx_kernel(const float* __restrict__ kp, const float* __restrict__ vp)
{
    __shared__ __align__(16) float s_ek[2][CHUNK * EK_STR]; // 8.7 KB natural [n][d]
    __shared__ __align__(16) float s_v [2][CHUNK * V_STR];  // 8.7 KB natural [n][e]
    __shared__ __align__(16) float s_red[4 * DIM];          // 1 KB

    const int tid = threadIdx.x;
    const int w = tid >> 5, l = tid & 31;
    const int dbase = 32 * w + 8 * (l >> 3);
    const int eg = l & 7;
    const int hh = tid >> 4, dcol = tid & 15;        // staging coords (hh 0..3)
    const int split = blockIdx.x, bh = blockIdx.y;
    const size_t base = ((size_t)bh * SEQ + (size_t)split * RPS) * DIM;

    u64 accD[4][4], accA[4][4];                      // [d-pair][e-pair]
#pragma unroll
    for (int i = 0; i < 4; i++)
#pragma unroll
        for (int j = 0; j < 4; j++) { accD[i][j] = 0ull; accA[i][j] = 0ull; }
    float4 cs = make_float4(0.f, 0.f, 0.f, 0.f);     // colsum for d=4dcol..+3

    // ---- prologue: stage chunk 0 ----
    {
#pragma unroll
        for (int r = 0; r < 4; r++) {
            const int nl = 4 * r + hh;               // 0..15
            cp16(&s_v[0][nl * V_STR + 4 * dcol],
                 vp + base + (size_t)nl * DIM + 4 * dcol);
        }
        asm volatile("cp.async.commit_group;");
        float4 kk[4];
#pragma unroll
        for (int r = 0; r < 4; r++) {
            const int nl = 4 * r + hh;
            kk[r] = *(const float4*)(kp + base + (size_t)nl * DIM + 4 * dcol);
        }
#pragma unroll
        for (int r = 0; r < 4; r++) {
            const int nl = 4 * r + hh;
            const float e0 = __expf(kk[r].x), e1 = __expf(kk[r].y),
                        e2 = __expf(kk[r].z), e3 = __expf(kk[r].w);
            cs.x += e0; cs.y += e1; cs.z += e2; cs.w += e3;
            *(float4*)&s_ek[0][nl * EK_STR + 4 * dcol] = make_float4(e0, e1, e2, e3);
        }
        asm volatile("cp.async.wait_group 0;");
        __syncthreads();
    }

    for (int ch = 0; ch < NCH; ch++) {
        const int p = ch & 1;
        float4 kk[4];
        if (ch + 1 < NCH) {
            const size_t nb = base + (size_t)(ch + 1) * CHUNK * DIM;
#pragma unroll
            for (int r = 0; r < 4; r++) {
                const int nl = 4 * r + hh;
                cp16(&s_v[1 - p][nl * V_STR + 4 * dcol],
                     vp + nb + (size_t)nl * DIM + 4 * dcol);
            }
            asm volatile("cp.async.commit_group;");
#pragma unroll
            for (int r = 0; r < 4; r++) {
                const int nl = 4 * r + hh;
                kk[r] = *(const float4*)(kp + nb + (size_t)nl * DIM + 4 * dcol);
            }
        }

        // ---- inner: rank-1 updates on buffer p ----
        const float* ekb = s_ek[p];
        const float* vb  = s_v[p];
#pragma unroll 8
        for (int n = 0; n < CHUNK; n++) {
            const float* ekn = ekb + n * EK_STR + dbase;
            const ulonglong2 dA = *(const ulonglong2*)(ekn);     // (d0,d1),(d2,d3)
            const ulonglong2 dB = *(const ulonglong2*)(ekn + 4); // (d4,d5),(d6,d7)
            const u64 s0 = swap2(dA.x), s1 = swap2(dA.y);
            const u64 s2 = swap2(dB.x), s3 = swap2(dB.y);
            const float* vn = vb + n * V_STR;
            const ulonglong2 v0 = *(const ulonglong2*)(vn + 4 * eg);      // (e0,e1),(e2,e3)
            const ulonglong2 v1 = *(const ulonglong2*)(vn + 32 + 4 * eg); // (E0,E1),(E2,E3)

            fma2(accD[0][0], dA.x, v0.x); fma2(accA[0][0], s0, v0.x);
            fma2(accD[0][1], dA.x, v0.y); fma2(accA[0][1], s0, v0.y);
            fma2(accD[0][2], dA.x, v1.x); fma2(accA[0][2], s0, v1.x);
            fma2(accD[0][3], dA.x, v1.y); fma2(accA[0][3], s0, v1.y);
            fma2(accD[1][0], dA.y, v0.x); fma2(accA[1][0], s1, v0.x);
            fma2(accD[1][1], dA.y, v0.y); fma2(accA[1][1], s1, v0.y);
            fma2(accD[1][2], dA.y, v1.x); fma2(accA[1][2], s1, v1.x);
            fma2(accD[1][3], dA.y, v1.y); fma2(accA[1][3], s1, v1.y);
            fma2(accD[2][0], dB.x, v0.x); fma2(accA[2][0], s2, v0.x);
            fma2(accD[2][1], dB.x, v0.y); fma2(accA[2][1], s2, v0.y);
            fma2(accD[2][2], dB.x, v1.x); fma2(accA[2][2], s2, v1.x);
            fma2(accD[2][3], dB.x, v1.y); fma2(accA[2][3], s2, v1.y);
            fma2(accD[3][0], dB.y, v0.x); fma2(accA[3][0], s3, v0.x);
            fma2(accD[3][1], dB.y, v0.y); fma2(accA[3][1], s3, v0.y);
            fma2(accD[3][2], dB.y, v1.x); fma2(accA[3][2], s3, v1.x);
            fma2(accD[3][3], dB.y, v1.y); fma2(accA[3][3], s3, v1.y);
        }

        if (ch + 1 < NCH) {
#pragma unroll
            for (int r = 0; r < 4; r++) {
                const int nl = 4 * r + hh;
                const float e0 = __expf(kk[r].x), e1 = __expf(kk[r].y),
                            e2 = __expf(kk[r].z), e3 = __expf(kk[r].w);
                cs.x += e0; cs.y += e1; cs.z += e2; cs.w += e3;
                *(float4*)&s_ek[1 - p][nl * EK_STR + 4 * dcol] =
                    make_float4(e0, e1, e2, e3);
            }
            asm volatile("cp.async.wait_group 0;");
        }
        __syncthreads();
    }

    // ---- colsum partial ----
    *(float4*)&s_red[hh * DIM + 4 * dcol] = cs;
    __syncthreads();
    const int pbase = bh * SPLIT + split;
    {
        float s = 0.f;
#pragma unroll
        for (int y = 0; y < 4; y++) s += s_red[y * DIM + tid];
        g_cs_partial[pbase * DIM + tid] = s;
    }

    // ---- context partial (plain [d][e]) ----
    float* cp = g_ctx_partial + (size_t)pbase * DIM * DIM;
#pragma unroll
    for (int dp = 0; dp < 4; dp++) {
        const float2 D0 = unpack2(accD[dp][0]), A0 = unpack2(accA[dp][0]);
        const float2 D1 = unpack2(accD[dp][1]), A1 = unpack2(accA[dp][1]);
        const float2 D2 = unpack2(accD[dp][2]), A2 = unpack2(accA[dp][2]);
        const float2 D3 = unpack2(accD[dp][3]), A3 = unpack2(accA[dp][3]);
        float* r0 = cp + (size_t)(dbase + 2 * dp) * DIM;
        float* r1 = r0 + DIM;
        *(float4*)(r0 + 4 * eg)      = make_float4(D0.x, A0.y, D1.x, A1.y);
        *(float4*)(r0 + 32 + 4 * eg) = make_float4(D2.x, A2.y, D3.x, A3.y);
        *(float4*)(r1 + 4 * eg)      = make_float4(A0.x, D0.y, A1.x, D1.y);
        *(float4*)(r1 + 32 + 4 * eg) = make_float4(A2.x, D2.y, A3.x, D3.y);
    }
}

// ============================================================================
// Kernel 2: reduce split partials, normalize, emit NATURAL fp32 context.
// ============================================================================
__global__ __launch_bounds__(256)
void reduce_kernel()
{
    const int bh = blockIdx.x, tid = threadIdx.x;
    __shared__ float inv[DIM];
    if (tid < DIM) {
        float s = 0.f;
#pragma unroll
        for (int sp = 0; sp < SPLIT; sp++)
            s += g_cs_partial[(bh * SPLIT + sp) * DIM + tid];
        inv[tid] = 1.0f / (s * (1.0f + EPSF));
    }
    __syncthreads();
#pragma unroll
    for (int r = 0; r < 4; r++) {
        const int i4 = r * 256 + tid;
        float4 s = make_float4(0.f, 0.f, 0.f, 0.f);
#pragma unroll
        for (int sp = 0; sp < SPLIT; sp++) {
            const float4 p = *(const float4*)(g_ctx_partial +
                (size_t)(bh * SPLIT + sp) * DIM * DIM + 4 * i4);
            s.x += p.x; s.y += p.y; s.z += p.z; s.w += p.w;
        }
        const float iv = inv[i4 >> 4];
        s.x *= iv; s.y *= iv; s.z *= iv; s.w *= iv;
        *(float4*)(g_ctx + (size_t)bh * DIM * DIM + 4 * i4) = s;
    }
}

// ============================================================================
// Kernel 3: out = rowsoftmax(Q) @ ctx.  128 threads, 128 n-rows per block.
// (exact R6 version — measured best)
// ============================================================================
#define ONB    128
#define PT_STR 128
#define C_STR  68

__global__ __launch_bounds__(128, 4)
void out_kernel(const float* __restrict__ qp, float* __restrict__ outp)
{
    __shared__ __align__(16) float s_pT[DIM * PT_STR]; // 32 KB  p^T [d][n]
    __shared__ __align__(16) float s_c [DIM * C_STR];  // 17 KB  natural ctx [d][e]

    const int tid = threadIdx.x;
    const int w = tid >> 5, l = tid & 31;
    const int nbase = 32 * w + 8 * (l >> 3);
    const int eg = l & 7;
    const int nb = blockIdx.x, bh = blockIdx.y;

    // stage natural ctx (padded stride)
    {
        const float4* src = (const float4*)(g_ctx + (size_t)bh * DIM * DIM);
#pragma unroll
        for (int r = 0; r < 8; r++) {
            const int i = r * 128 + tid;             // i = d*16 + c
            const int d = i >> 4, c = i & 15;
            *(float4*)&s_c[d * C_STR + 4 * c] = src[i];
        }
    }

    // row softmax of q: 2 threads per row, 2 passes of 64 rows
#pragma unroll
    for (int pass = 0; pass < 2; pass++) {
        const int row = 64 * pass + (tid >> 1), part = tid & 1;
        const float* qr = qp + ((size_t)bh * SEQ + (size_t)nb * ONB + row) * DIM + part * 32;
        float e[32];
#pragma unroll
        for (int i = 0; i < 8; i++) {
            const float4 a = *(const float4*)(qr + 4 * i);
            e[4*i] = a.x; e[4*i+1] = a.y; e[4*i+2] = a.z; e[4*i+3] = a.w;
        }
        float m = e[0];
#pragma unroll
        for (int i = 1; i < 32; i++) m = fmaxf(m, e[i]);
        m = fmaxf(m, __shfl_xor_sync(0xffffffffu, m, 1));
        float s = 0.f;
#pragma unroll
        for (int i = 0; i < 32; i++) { e[i] = __expf(e[i] - m); s += e[i]; }
        s += __shfl_xor_sync(0xffffffffu, s, 1);
        const float rinv = 1.0f / s;
#pragma unroll
        for (int i = 0; i < 32; i++)
            s_pT[(32 * part + i) * PT_STR + row] = e[i] * rinv;
    }
    __syncthreads();

    // GEMM: out[n][e] = sum_d p[n][d] * ctx[d][e]
    u64 accD[4][4], accA[4][4];                      // [n-pair][e-pair]
#pragma unroll
    for (int i = 0; i < 4; i++)
#pragma unroll
        for (int j = 0; j < 4; j++) { accD[i][j] = 0ull; accA[i][j] = 0ull; }

#pragma unroll 8
    for (int d = 0; d < DIM; d++) {
        const float* pd = s_pT + d * PT_STR + nbase;
        const ulonglong2 pA = *(const ulonglong2*)(pd);       // (n0,n1),(n2,n3)
        const ulonglong2 pB = *(const ulonglong2*)(pd + 4);   // (n4,n5),(n6,n7)
        const u64 sA0 = swap2(pA.x), sA1 = swap2(pA.y);
        const u64 sB0 = swap2(pB.x), sB1 = swap2(pB.y);
        const float* cd = s_c + d * C_STR;
        const ulonglong2 c0 = *(const ulonglong2*)(cd + 4 * eg);      // (e0,e1),(e2,e3)
        const ulonglong2 c1 = *(const ulonglong2*)(cd + 32 + 4 * eg); // (E0,E1),(E2,E3)
        fma2(accD[0][0], pA.x, c0.x); fma2(accA[0][0], sA0, c0.x);
        fma2(accD[0][1], pA.x, c0.y); fma2(accA[0][1], sA0, c0.y);
        fma2(accD[0][2], pA.x, c1.x); fma2(accA[0][2], sA0, c1.x);
        fma2(accD[0][3], pA.x, c1.y); fma2(accA[0][3], sA0, c1.y);
        fma2(accD[1][0], pA.y, c0.x); fma2(accA[1][0], sA1, c0.x);
        fma2(accD[1][1], pA.y, c0.y); fma2(accA[1][1], sA1, c0.y);
        fma2(accD[1][2], pA.y, c1.x); fma2(accA[1][2], sA1, c1.x);
        fma2(accD[1][3], pA.y, c1.y); fma2(accA[1][3], sA1, c1.y);
        fma2(accD[2][0], pB.x, c0.x); fma2(accA[2][0], sB0, c0.x);
        fma2(accD[2][1], pB.x, c0.y); fma2(accA[2][1], sB0, c0.y);
        fma2(accD[2][2], pB.x, c1.x); fma2(accA[2][2], sB0, c1.x);
        fma2(accD[2][3], pB.x, c1.y); fma2(accA[2][3], sB0, c1.y);
        fma2(accD[3][0], pB.y, c0.x); fma2(accA[3][0], sB1, c0.x);
        fma2(accD[3][1], pB.y, c0.y); fma2(accA[3][1], sB1, c0.y);
        fma2(accD[3][2], pB.y, c1.x); fma2(accA[3][2], sB1, c1.x);
        fma2(accD[3][3], pB.y, c1.y); fma2(accA[3][3], sB1, c1.y);
    }

    // epilogue: block (n0,n1)x(e0,e1): row n0 = (D.x, A.y); row n1 = (A.x, D.y)
    const size_t obase = ((size_t)bh * SEQ + (size_t)nb * ONB) * DIM;
#pragma unroll
    for (int p = 0; p < 4; p++) {
        const float2 D0 = unpack2(accD[p][0]), A0 = unpack2(accA[p][0]);
        const float2 D1 = unpack2(accD[p][1]), A1 = unpack2(accA[p][1]);
        const float2 D2 = unpack2(accD[p][2]), A2 = unpack2(accA[p][2]);
        const float2 D3 = unpack2(accD[p][3]), A3 = unpack2(accA[p][3]);
        float* r0 = outp + obase + (size_t)(nbase + 2 * p) * DIM;
        float* r1 = r0 + DIM;
        *(float4*)(r0 + 4 * eg)      = make_float4(D0.x, A0.y, D1.x, A1.y);
        *(float4*)(r0 + 32 + 4 * eg) = make_float4(D2.x, A2.y, D3.x, A3.y);
        *(float4*)(r1 + 4 * eg)      = make_float4(A0.x, D0.y, A1.x, D1.y);
        *(float4*)(r1 + 32 + 4 * eg) = make_float4(A2.x, D2.y, A3.x, D3.y);
    }
}

// ============================================================================
extern "C" void kernel_launch(void* const* d_in, const int* in_sizes, int n_in,
                              void* d_out, int out_size)
{
    const float* q = (const float*)d_in[0];
    const float* k = (const float*)d_in[1];
    const float* v = (const float*)d_in[2];
    float* out = (float*)d_out;

    ctx_kernel  <<<dim3(SPLIT, BHN), 64>>>(k, v);
    reduce_kernel<<<BHN, 256>>>();
    out_kernel  <<<dim3(SEQ / ONB, BHN), 128>>>(q, out);
}